// round 16
// baseline (speedup 1.0000x reference)
#include <cuda_runtime.h>
#include <math.h>
#include <stdint.h>

#define NTOK 32768
#define CCH  128
#define CF   512
#define NHEADS 8
#define HD   16
#define EPSF 1e-5f
#define INVN (1.0f/32768.0f)

// ---------------- scratch (device globals) ----------------
__device__ uint32_t g_xt[NTOK*CCH];      // x^T as tf32 bits [n][128]
__device__ float    g_q[NHEADS*NTOK*HD]; // [h][n][16] f32
__device__ float    g_k[NHEADS*NTOK*HD];
__device__ float    g_v[NHEADS*NTOK*HD];
__device__ uint32_t g_attn[NTOK*CCH];    // attn out, tf32 bits [n][128]
__device__ float    g_y[NTOK*CCH];       // proj out f32 [n][128]
__device__ uint32_t g_t[NTOK*CCH];       // norm1(g_y) tf32 bits
__device__ uint32_t g_h1[NTOK*CF];       // gelu(ffn1) tf32 bits [n][512]
__device__ float    g_u[NTOK*CCH];       // ffn2 + residual f32
__device__ uint32_t g_wq[384*128];       // tf32 weights
__device__ uint32_t g_wp[128*128];
__device__ uint32_t g_w1[512*128];
__device__ uint32_t g_w2[128*512];
__device__ float    g_part[256*256];
__device__ float    g_stats[2*CCH];

__device__ __forceinline__ uint32_t f2tf32(float f) {
    uint32_t u; asm("cvt.rna.tf32.f32 %0, %1;" : "=r"(u) : "f"(f)); return u;
}
__device__ __forceinline__ float gelu_tanh(float x) {
    const float c0 = 0.7978845608028654f;
    float x3 = x*x*x;
    return 0.5f*x*(1.0f + tanhf(c0*(x + 0.044715f*x3)));
}
__device__ __forceinline__ void mma_tf32(float c[4], const uint32_t a[4], const uint32_t b[2]) {
    asm volatile(
        "mma.sync.aligned.m16n8k8.row.col.f32.tf32.tf32.f32 "
        "{%0,%1,%2,%3}, {%4,%5,%6,%7}, {%8,%9}, {%0,%1,%2,%3};"
        : "+f"(c[0]), "+f"(c[1]), "+f"(c[2]), "+f"(c[3])
        : "r"(a[0]), "r"(a[1]), "r"(a[2]), "r"(a[3]), "r"(b[0]), "r"(b[1]));
}
__device__ __forceinline__ uint32_t smem_u32(const void* p) {
    uint32_t a;
    asm("{ .reg .u64 t; cvta.to.shared.u64 t, %1; cvt.u32.u64 %0, t; }" : "=r"(a) : "l"(p));
    return a;
}
__device__ __forceinline__ void cp16(uint32_t s, const void* g) {
    asm volatile(
        "{\n\t.reg .u64 ga;\n\tcvta.to.global.u64 ga, %1;\n\t"
        "cp.async.cg.shared.global [%0], [ga], 16;\n\t}"
        :: "r"(s), "l"(g) : "memory");
}
#define CP_COMMIT()  asm volatile("cp.async.commit_group;" ::: "memory")
#define CP_WAIT(n)   asm volatile("cp.async.wait_group %0;" :: "n"(n) : "memory")

// ---------------- all-weights conversion f32 -> tf32 bits, ONE launch ------
// dst arrays selected in device code (host-side __device__ symbol decay passes
// the host shadow address — the round-9/11 zero-output bug).
__global__ __launch_bounds__(256) void cvt_all(const float* __restrict__ wq,
                                               const float* __restrict__ wp,
                                               const float* __restrict__ w1,
                                               const float* __restrict__ w2) {
    int i = blockIdx.x*256 + threadIdx.x;              // 0 .. 196607
    if (i < 49152)        g_wq[i]          = f2tf32(wq[i]);
    else if (i < 65536)   g_wp[i - 49152]  = f2tf32(wp[i - 49152]);
    else if (i < 131072)  g_w1[i - 65536]  = f2tf32(w1[i - 65536]);
    else                  g_w2[i - 131072] = f2tf32(w2[i - 131072]);
}

// ---------------- transpose x [C][N] -> g_xt tf32 [N][C] ----------------
__global__ __launch_bounds__(256) void transpose_x(const float* __restrict__ x) {
    __shared__ float tile[32][33];
    const int n0 = blockIdx.x*32, c0 = blockIdx.y*32;
    const int tx = threadIdx.x & 31, ty = threadIdx.x >> 5;
#pragma unroll
    for (int r = 0; r < 32; r += 8)
        tile[ty+r][tx] = x[(size_t)(c0+ty+r)*NTOK + n0 + tx];
    __syncthreads();
#pragma unroll
    for (int r = 0; r < 32; r += 8)
        g_xt[(size_t)(n0+ty+r)*CCH + c0 + tx] = f2tf32(tile[tx][ty+r]);
}

// ---------------- cp.async double-buffered tf32 GEMM, 128x128 tile --------
#define AR20 (128*20)
#define STG2 (2*AR20)      // A + B per stage = 5120 u32 (20 KB); x2 = 40 KB

template<int KDIM, int MODE>
__global__ __launch_bounds__(256) void mma_gemm(const float* __restrict__ bias) {
    __shared__ uint32_t dsm[2*STG2];
    __shared__ float red[1024];
    __shared__ float m_s[128], r_s[128];

    const uint32_t* Ag = (MODE==0) ? g_xt : (MODE==1) ? g_attn : (MODE==2) ? g_t : g_h1;
    const uint32_t* Bg = (MODE==0) ? g_wq : (MODE==1) ? g_wp   : (MODE==2) ? g_w1 : g_w2;

    const int tx = threadIdx.x;
    const int w  = tx >> 5, lane = tx & 31;
    const int wm = w >> 1, wn = w & 1;
    const int g  = lane >> 2, tq = lane & 3;
    const int n0 = blockIdx.x * 128;
    const int o0 = blockIdx.y * 128;
    const uint32_t sbase = smem_u32(dsm);
    const int rr = tx >> 2, k4 = tx & 3;
    const int NCH = KDIM / 16;

    if (MODE == 3 && tx < 128) {
        float m = g_stats[tx] * INVN;
        float var = g_stats[128+tx] * INVN - m*m;
        m_s[tx] = m;
        r_s[tx] = rsqrtf(var + EPSF);
    }

    auto stage = [&](int s, int kb) {
        const uint32_t sa = sbase + (uint32_t)s*STG2*4;
        const uint32_t sb = sa + AR20*4;
#pragma unroll
        for (int i = 0; i < 2; i++) {
            const int n = i*64 + rr;
            cp16(sa + (uint32_t)(n*20 + k4*4)*4, Ag + (size_t)(n0+n)*KDIM + kb + k4*4);
            cp16(sb + (uint32_t)(n*20 + k4*4)*4, Bg + (size_t)(o0+n)*KDIM + kb + k4*4);
        }
        CP_COMMIT();
    };

    float c[2][8][4];
#pragma unroll
    for (int mt = 0; mt < 2; mt++)
#pragma unroll
        for (int nt = 0; nt < 8; nt++)
#pragma unroll
            for (int i = 0; i < 4; i++) c[mt][nt][i] = 0.f;

    stage(0, 0);
    stage(1, 16);

    for (int ch = 0; ch < NCH; ch++) {
        if (ch < NCH-1) CP_WAIT(1); else CP_WAIT(0);
        __syncthreads();
        const uint32_t* As = dsm + (ch & 1)*STG2;
        const uint32_t* Bs = As + AR20;
#pragma unroll
        for (int kt = 0; kt < 2; kt++) {
            const int kc = kt*8 + tq;
            uint32_t a[2][4], b[8][2];
#pragma unroll
            for (int mt = 0; mt < 2; mt++) {
                const int rb = (wm*32 + mt*16 + g)*20;
                a[mt][0] = As[rb + kc];
                a[mt][1] = As[rb + 8*20 + kc];
                a[mt][2] = As[rb + kc + 4];
                a[mt][3] = As[rb + 8*20 + kc + 4];
            }
#pragma unroll
            for (int nt = 0; nt < 8; nt++) {
                const int rb = (wn*64 + nt*8 + g)*20;
                b[nt][0] = Bs[rb + kc];
                b[nt][1] = Bs[rb + kc + 4];
            }
#pragma unroll
            for (int mt = 0; mt < 2; mt++)
#pragma unroll
                for (int nt = 0; nt < 8; nt++)
                    mma_tf32(c[mt][nt], a[mt], b[nt]);
        }
        __syncthreads();
        if (ch + 2 < NCH) stage(ch & 1, (ch+2)*16);
    }

    // ---- epilogue ----
    float s[8][2], q2[8][2];
    if (MODE == 1 || MODE == 3) {
#pragma unroll
        for (int nt = 0; nt < 8; nt++) { s[nt][0]=s[nt][1]=q2[nt][0]=q2[nt][1]=0.f; }
    }

#pragma unroll
    for (int mt = 0; mt < 2; mt++) {
#pragma unroll
        for (int nt = 0; nt < 8; nt++) {
            const int colb = (wn*8 + nt)*8 + tq*2;
            const float b0 = bias[o0 + colb];
            const float b1 = bias[o0 + colb + 1];
            const int row0 = n0 + (wm*2 + mt)*16 + g;
#pragma unroll
            for (int half = 0; half < 2; half++) {
                const int row = row0 + half*8;
                float v0 = c[mt][nt][half*2+0] + b0;
                float v1 = c[mt][nt][half*2+1] + b1;
                if (MODE == 2) {
                    v0 = gelu_tanh(v0); v1 = gelu_tanh(v1);
                } else if (MODE == 3) {
                    const float2 r2 = *(const float2*)&g_y[(size_t)row*128 + colb];
                    v0 += (r2.x - m_s[colb])   * r_s[colb];
                    v1 += (r2.y - m_s[colb+1]) * r_s[colb+1];
                }
                if (MODE == 0) {
                    const int by = blockIdx.y;
                    float* base = (by == 0) ? g_q : (by == 1) ? g_k : g_v;
                    *(float2*)&base[(size_t)(colb>>4)*(NTOK*HD) + (size_t)row*16 + (colb&15)]
                        = make_float2(v0, v1);
                } else if (MODE == 1) {
                    *(float2*)&g_y[(size_t)row*128 + colb] = make_float2(v0, v1);
                } else if (MODE == 2) {
                    *(uint2*)&g_h1[(size_t)row*512 + o0 + colb]
                        = make_uint2(f2tf32(v0), f2tf32(v1));
                } else {
                    *(float2*)&g_u[(size_t)row*128 + colb] = make_float2(v0, v1);
                }
                if (MODE == 1 || MODE == 3) {
                    s[nt][0] += v0; s[nt][1] += v1;
                    q2[nt][0] += v0*v0; q2[nt][1] += v1*v1;
                }
            }
        }
    }

    if (MODE == 1 || MODE == 3) {
#pragma unroll
        for (int nt = 0; nt < 8; nt++) {
#pragma unroll
            for (int j = 0; j < 2; j++) {
                float a0 = s[nt][j], a1 = q2[nt][j];
#pragma unroll
                for (int off = 4; off < 32; off <<= 1) {
                    a0 += __shfl_xor_sync(0xffffffffu, a0, off);
                    a1 += __shfl_xor_sync(0xffffffffu, a1, off);
                }
                if (g == 0) {
                    const int col = (wn*8 + nt)*8 + tq*2 + j;
                    red[col*4 + wm]       = a0;
                    red[512 + col*4 + wm] = a1;
                }
            }
        }
        __syncthreads();
        if (tx < 128) {
            const int col = tx;
            float ssum = 0.f, ssq = 0.f;
#pragma unroll
            for (int wm2 = 0; wm2 < 4; wm2++) {
                ssum += red[col*4 + wm2];
                ssq  += red[512 + col*4 + wm2];
            }
            g_part[blockIdx.x*256 + col]       = ssum;
            g_part[blockIdx.x*256 + 128 + col] = ssq;
        }
    }
}

// ---------------- attention: smem-staged, split score/AV phases -----------
// K tile: quad-split layout K4s[((c4*9+col)*33+row)*4] so phase-A reads are
//   4x LDS.128 per lane (bank-quad = (c4+col+row) mod 8, max ~3-way).
// V tile: row stride 16, plane 524 (float4 staging, LDS.64 phase-B reads).
#define RSV  16
#define PSV  524
__global__ __launch_bounds__(256) void attn_smem(const float* __restrict__ rpb) {
    __shared__ float K4s[4*9*33*4];   // 19008 B
    __shared__ float Vs[9*PSV];       // 18864 B
    __shared__ float Qs[32*16];
    __shared__ float Ps[32*28];       // scaled probs per z
    __shared__ float rpbs[125];

    const int cw = blockIdx.x;
    const int h  = blockIdx.y;
    const int hh = cw >> 5, ww = cw & 31;
    const int sh = min(max(hh-1, 0), 29);
    const int sw = min(max(ww-1, 0), 29);
    const int t = threadIdx.x;
    const size_t hb = (size_t)h * (NTOK*HD);

    for (int idx = t; idx < 1152; idx += 256) {
        const int col = idx >> 7;
        const int rem = idx & 127;
        const int a = col/3, b = col - a*3;
        const int nbase = ((sh+a)*32 + (sw+b))*32;
        const int z = rem >> 2, c4 = rem & 3;
        float4 kv = *(const float4*)&g_k[hb + (size_t)nbase*16 + rem*4];
        float4 vv = *(const float4*)&g_v[hb + (size_t)nbase*16 + rem*4];
        *(float4*)&K4s[((c4*9 + col)*33 + z)*4] = kv;
        *(float4*)&Vs[col*PSV + z*RSV + c4*4] = vv;
    }
    if (t < 128) {
        const int z = t >> 2, c4 = t & 3;
        float4 qv = *(const float4*)&g_q[hb + (size_t)(cw*32 + z)*16 + c4*4];
        float* dq = &Qs[z*16 + c4*4];
        dq[0]=qv.x*0.25f; dq[1]=qv.y*0.25f; dq[2]=qv.z*0.25f; dq[3]=qv.w*0.25f;
    }
    if (t < 125) rpbs[t] = rpb[h*125 + t];
    __syncthreads();

    // ---- phase A: scores + softmax, store scaled probs ----
    const int w = t >> 5, lane = t & 31;
    int a = 0, b = 0, jz = 0;
    if (lane < 27) { a = lane/9; b = (lane - a*9)/3; jz = lane - a*9 - b*3; }
    const int colp = a*3 + b;
    const int rh = sh + a - hh + 2;
    const int rw = sw + b - ww + 2;

#pragma unroll 1
    for (int tz = 0; tz < 4; tz++) {
        const int z  = w*4 + tz;
        const int sz = min(max(z-1, 0), 29);
        float sc = -1e30f;
        if (lane < 27) {
            const int srow = sz + jz;
            const float4* qr = (const float4*)&Qs[z*16];
            const float4 q0 = qr[0], q1 = qr[1], q2 = qr[2], q3 = qr[3];
            const float4 k0 = *(const float4*)&K4s[((0*9 + colp)*33 + srow)*4];
            const float4 k1 = *(const float4*)&K4s[((1*9 + colp)*33 + srow)*4];
            const float4 k2 = *(const float4*)&K4s[((2*9 + colp)*33 + srow)*4];
            const float4 k3 = *(const float4*)&K4s[((3*9 + colp)*33 + srow)*4];
            float sdot = q0.x*k0.x + q0.y*k0.y + q0.z*k0.z + q0.w*k0.w
                       + q1.x*k1.x + q1.y*k1.y + q1.z*k1.z + q1.w*k1.w
                       + q2.x*k2.x + q2.y*k2.y + q2.z*k2.z + q2.w*k2.w
                       + q3.x*k3.x + q3.y*k3.y + q3.z*k3.z + q3.w*k3.w;
            const int rz = srow - z + 2;
            sc = sdot + rpbs[(rh*5 + rw)*5 + rz];
        }
        float mx = sc;
#pragma unroll
        for (int off = 16; off; off >>= 1) mx = fmaxf(mx, __shfl_xor_sync(0xffffffffu, mx, off));
        float p = (lane < 27) ? __expf(sc - mx) : 0.f;
        float su = p;
#pragma unroll
        for (int off = 16; off; off >>= 1) su += __shfl_xor_sync(0xffffffffu, su, off);
        if (lane < 27) Ps[z*28 + lane] = p / su;
    }
    __syncthreads();

    // ---- phase B: AV, thread = (z, channel-pair) ----
    const int z2 = t >> 3;          // 0..31
    const int cp = t & 7;           // 0..7
    const int sz2 = min(max(z2-1, 0), 29);
    float ax = 0.f, ay = 0.f;
#pragma unroll
    for (int j = 0; j < 27; j++) {
        const int cj = j / 3;       // compile-time
        const int zj = j % 3;       // compile-time
        const float pj = Ps[z2*28 + j];
        const float2 v2 = *(const float2*)&Vs[cj*PSV + (sz2+zj)*RSV + cp*2];
        ax += pj * v2.x;
        ay += pj * v2.y;
    }
    *(uint2*)&g_attn[(size_t)(cw*32 + z2)*128 + h*16 + cp*2]
        = make_uint2(f2tf32(ax), f2tf32(ay));
}

// ---------------- final reduce: 256 partial blocks -> stats (1024 thr) ----
__global__ __launch_bounds__(1024) void reduce_final() {
    __shared__ float red[1024];
    const int t = threadIdx.x;
    const int slot = t & 255, part = t >> 8;   // 4 parts x 64 blocks
    float s = 0.f;
#pragma unroll 8
    for (int bx = part*64; bx < part*64 + 64; bx++) s += g_part[bx*256 + slot];
    red[part*256 + slot] = s;
    __syncthreads();
    if (t < 256) g_stats[t] = red[t] + red[256+t] + red[512+t] + red[768+t];
}

// ---------------- norm1 applied to g_y -> g_t (tf32 bits) ----------------
__global__ __launch_bounds__(256) void norm_tf32() {
    const int idx = blockIdx.x*256 + threadIdx.x;
    const int c = idx & 127;
    float m   = g_stats[c]     * INVN;
    float var = g_stats[c+128] * INVN - m*m;
    g_t[idx] = f2tf32((g_y[idx] - m) * rsqrtf(var + EPSF));
}

// ---------------- final instance-norm + transpose to [C][N] ----------------
__global__ __launch_bounds__(256) void norm_transpose(float* __restrict__ out) {
    __shared__ float tile[32][33];
    const int n0 = blockIdx.x*32, c0 = blockIdx.y*32;
    const int txx = threadIdx.x & 31, tyy = threadIdx.x >> 5;
    const int c = c0 + txx;
    float m   = g_stats[c]     * INVN;
    float var = g_stats[c+128] * INVN - m*m;
    float rs  = rsqrtf(var + EPSF);
#pragma unroll
    for (int r = 0; r < 32; r += 8)
        tile[tyy+r][txx] = (g_u[(size_t)(n0+tyy+r)*128 + c] - m) * rs;
    __syncthreads();
#pragma unroll
    for (int r = 0; r < 32; r += 8)
        out[(size_t)(c0+tyy+r)*NTOK + n0 + txx] = tile[txx][tyy+r];
}

// ---------------- launch ----------------
extern "C" void kernel_launch(void* const* d_in, const int* in_sizes, int n_in,
                              void* d_out, int out_size) {
    const float* x      = (const float*)d_in[0];
    const float* w_qkv  = (const float*)d_in[1];
    const float* b_qkv  = (const float*)d_in[2];
    const float* rpb    = (const float*)d_in[3];
    const float* w_proj = (const float*)d_in[4];
    const float* b_proj = (const float*)d_in[5];
    const float* w_ffn1 = (const float*)d_in[6];
    const float* b_ffn1 = (const float*)d_in[7];
    const float* w_ffn2 = (const float*)d_in[8];
    const float* b_ffn2 = (const float*)d_in[9];
    float* out = (float*)d_out;

    cvt_all<<<768, 256>>>(w_qkv, w_proj, w_ffn1, w_ffn2);
    transpose_x<<<dim3(NTOK/32, CCH/32), 256>>>(x);
    mma_gemm<128,0><<<dim3(256, 3), 256>>>(b_qkv);
    attn_smem<<<dim3(1024, NHEADS), 256>>>(rpb);
    mma_gemm<128,1><<<dim3(256, 1), 256>>>(b_proj);
    reduce_final<<<1, 1024>>>();
    norm_tf32<<<NTOK*CCH/256, 256>>>();
    mma_gemm<128,2><<<dim3(256, 4), 256>>>(b_ffn1);
    mma_gemm<512,3><<<dim3(256, 1), 256>>>(b_ffn2);
    reduce_final<<<1, 1024>>>();
    norm_transpose<<<dim3(NTOK/32, CCH/32), 256>>>(out);
}

// round 17
// speedup vs baseline: 1.0352x; 1.0352x over previous
#include <cuda_runtime.h>
#include <math.h>
#include <stdint.h>

#define NTOK 32768
#define CCH  128
#define CF   512
#define NHEADS 8
#define HD   16
#define EPSF 1e-5f
#define INVN (1.0f/32768.0f)

// ---------------- scratch (device globals) ----------------
__device__ uint32_t g_xt[NTOK*CCH];      // x^T as tf32 bits [n][128]
__device__ float    g_q[NHEADS*NTOK*HD]; // [h][n][16] f32
__device__ float    g_k[NHEADS*NTOK*HD];
__device__ float    g_v[NHEADS*NTOK*HD];
__device__ uint32_t g_attn[NTOK*CCH];    // attn out, tf32 bits [n][128]
__device__ float    g_y[NTOK*CCH];       // proj out f32 [n][128]
__device__ uint32_t g_t[NTOK*CCH];       // norm1(g_y) tf32 bits
__device__ uint32_t g_h1[NTOK*CF];       // gelu(ffn1) tf32 bits [n][512]
__device__ float    g_u[NTOK*CCH];       // ffn2 + residual f32
__device__ uint32_t g_wq[384*128];       // tf32 weights
__device__ uint32_t g_wp[128*128];
__device__ uint32_t g_w1[512*128];
__device__ uint32_t g_w2[128*512];
__device__ float    g_part[256*256];
__device__ float    g_stats[2*CCH];

__device__ __forceinline__ uint32_t f2tf32(float f) {
    uint32_t u; asm("cvt.rna.tf32.f32 %0, %1;" : "=r"(u) : "f"(f)); return u;
}
__device__ __forceinline__ float gelu_tanh(float x) {
    const float c0 = 0.7978845608028654f;
    float x3 = x*x*x;
    return 0.5f*x*(1.0f + tanhf(c0*(x + 0.044715f*x3)));
}
__device__ __forceinline__ void mma_tf32(float c[4], const uint32_t a[4], const uint32_t b[2]) {
    asm volatile(
        "mma.sync.aligned.m16n8k8.row.col.f32.tf32.tf32.f32 "
        "{%0,%1,%2,%3}, {%4,%5,%6,%7}, {%8,%9}, {%0,%1,%2,%3};"
        : "+f"(c[0]), "+f"(c[1]), "+f"(c[2]), "+f"(c[3])
        : "r"(a[0]), "r"(a[1]), "r"(a[2]), "r"(a[3]), "r"(b[0]), "r"(b[1]));
}
__device__ __forceinline__ uint32_t smem_u32(const void* p) {
    uint32_t a;
    asm("{ .reg .u64 t; cvta.to.shared.u64 t, %1; cvt.u32.u64 %0, t; }" : "=r"(a) : "l"(p));
    return a;
}
__device__ __forceinline__ void cp16(uint32_t s, const void* g) {
    asm volatile(
        "{\n\t.reg .u64 ga;\n\tcvta.to.global.u64 ga, %1;\n\t"
        "cp.async.cg.shared.global [%0], [ga], 16;\n\t}"
        :: "r"(s), "l"(g) : "memory");
}
#define CP_COMMIT()  asm volatile("cp.async.commit_group;" ::: "memory")
#define CP_WAIT(n)   asm volatile("cp.async.wait_group %0;" :: "n"(n) : "memory")

// ---------------- all-weights conversion f32 -> tf32 bits, ONE launch ------
// dst arrays selected in device code (host-side __device__ symbol decay passes
// the host shadow address — the round-9/11 zero-output bug).
__global__ __launch_bounds__(256) void cvt_all(const float* __restrict__ wq,
                                               const float* __restrict__ wp,
                                               const float* __restrict__ w1,
                                               const float* __restrict__ w2) {
    int i = blockIdx.x*256 + threadIdx.x;              // 0 .. 196607
    if (i < 49152)        g_wq[i]          = f2tf32(wq[i]);
    else if (i < 65536)   g_wp[i - 49152]  = f2tf32(wp[i - 49152]);
    else if (i < 131072)  g_w1[i - 65536]  = f2tf32(w1[i - 65536]);
    else                  g_w2[i - 131072] = f2tf32(w2[i - 131072]);
}

// ---------------- transpose x [C][N] -> g_xt tf32 [N][C] ----------------
__global__ __launch_bounds__(256) void transpose_x(const float* __restrict__ x) {
    __shared__ float tile[32][33];
    const int n0 = blockIdx.x*32, c0 = blockIdx.y*32;
    const int tx = threadIdx.x & 31, ty = threadIdx.x >> 5;
#pragma unroll
    for (int r = 0; r < 32; r += 8)
        tile[ty+r][tx] = x[(size_t)(c0+ty+r)*NTOK + n0 + tx];
    __syncthreads();
#pragma unroll
    for (int r = 0; r < 32; r += 8)
        g_xt[(size_t)(n0+ty+r)*CCH + c0 + tx] = f2tf32(tile[tx][ty+r]);
}

// ---------------- cp.async double-buffered tf32 GEMM, 128x128 tile --------
#define AR20 (128*20)
#define STG2 (2*AR20)      // A + B per stage = 5120 u32 (20 KB); x2 = 40 KB

template<int KDIM, int MODE>
__global__ __launch_bounds__(256) void mma_gemm(const float* __restrict__ bias) {
    __shared__ uint32_t dsm[2*STG2];
    __shared__ float red[1024];
    __shared__ float m_s[128], r_s[128];

    const uint32_t* Ag = (MODE==0) ? g_xt : (MODE==1) ? g_attn : (MODE==2) ? g_t : g_h1;
    const uint32_t* Bg = (MODE==0) ? g_wq : (MODE==1) ? g_wp   : (MODE==2) ? g_w1 : g_w2;

    const int tx = threadIdx.x;
    const int w  = tx >> 5, lane = tx & 31;
    const int wm = w >> 1, wn = w & 1;
    const int g  = lane >> 2, tq = lane & 3;
    const int n0 = blockIdx.x * 128;
    const int o0 = blockIdx.y * 128;
    const uint32_t sbase = smem_u32(dsm);
    const int rr = tx >> 2, k4 = tx & 3;
    const int NCH = KDIM / 16;

    if (MODE == 3 && tx < 128) {
        float m = g_stats[tx] * INVN;
        float var = g_stats[128+tx] * INVN - m*m;
        m_s[tx] = m;
        r_s[tx] = rsqrtf(var + EPSF);
    }

    auto stage = [&](int s, int kb) {
        const uint32_t sa = sbase + (uint32_t)s*STG2*4;
        const uint32_t sb = sa + AR20*4;
#pragma unroll
        for (int i = 0; i < 2; i++) {
            const int n = i*64 + rr;
            cp16(sa + (uint32_t)(n*20 + k4*4)*4, Ag + (size_t)(n0+n)*KDIM + kb + k4*4);
            cp16(sb + (uint32_t)(n*20 + k4*4)*4, Bg + (size_t)(o0+n)*KDIM + kb + k4*4);
        }
        CP_COMMIT();
    };

    float c[2][8][4];
#pragma unroll
    for (int mt = 0; mt < 2; mt++)
#pragma unroll
        for (int nt = 0; nt < 8; nt++)
#pragma unroll
            for (int i = 0; i < 4; i++) c[mt][nt][i] = 0.f;

    stage(0, 0);
    stage(1, 16);

    for (int ch = 0; ch < NCH; ch++) {
        if (ch < NCH-1) CP_WAIT(1); else CP_WAIT(0);
        __syncthreads();
        const uint32_t* As = dsm + (ch & 1)*STG2;
        const uint32_t* Bs = As + AR20;
#pragma unroll
        for (int kt = 0; kt < 2; kt++) {
            const int kc = kt*8 + tq;
            uint32_t a[2][4], b[8][2];
#pragma unroll
            for (int mt = 0; mt < 2; mt++) {
                const int rb = (wm*32 + mt*16 + g)*20;
                a[mt][0] = As[rb + kc];
                a[mt][1] = As[rb + 8*20 + kc];
                a[mt][2] = As[rb + kc + 4];
                a[mt][3] = As[rb + 8*20 + kc + 4];
            }
#pragma unroll
            for (int nt = 0; nt < 8; nt++) {
                const int rb = (wn*64 + nt*8 + g)*20;
                b[nt][0] = Bs[rb + kc];
                b[nt][1] = Bs[rb + kc + 4];
            }
#pragma unroll
            for (int mt = 0; mt < 2; mt++)
#pragma unroll
                for (int nt = 0; nt < 8; nt++)
                    mma_tf32(c[mt][nt], a[mt], b[nt]);
        }
        __syncthreads();
        if (ch + 2 < NCH) stage(ch & 1, (ch+2)*16);
    }

    // ---- epilogue ----
    float s[8][2], q2[8][2];
    if (MODE == 1 || MODE == 3) {
#pragma unroll
        for (int nt = 0; nt < 8; nt++) { s[nt][0]=s[nt][1]=q2[nt][0]=q2[nt][1]=0.f; }
    }

#pragma unroll
    for (int mt = 0; mt < 2; mt++) {
#pragma unroll
        for (int nt = 0; nt < 8; nt++) {
            const int colb = (wn*8 + nt)*8 + tq*2;
            const float b0 = bias[o0 + colb];
            const float b1 = bias[o0 + colb + 1];
            const int row0 = n0 + (wm*2 + mt)*16 + g;
#pragma unroll
            for (int half = 0; half < 2; half++) {
                const int row = row0 + half*8;
                float v0 = c[mt][nt][half*2+0] + b0;
                float v1 = c[mt][nt][half*2+1] + b1;
                if (MODE == 2) {
                    v0 = gelu_tanh(v0); v1 = gelu_tanh(v1);
                } else if (MODE == 3) {
                    const float2 r2 = *(const float2*)&g_y[(size_t)row*128 + colb];
                    v0 += (r2.x - m_s[colb])   * r_s[colb];
                    v1 += (r2.y - m_s[colb+1]) * r_s[colb+1];
                }
                if (MODE == 0) {
                    const int by = blockIdx.y;
                    float* base = (by == 0) ? g_q : (by == 1) ? g_k : g_v;
                    *(float2*)&base[(size_t)(colb>>4)*(NTOK*HD) + (size_t)row*16 + (colb&15)]
                        = make_float2(v0, v1);
                } else if (MODE == 1) {
                    *(float2*)&g_y[(size_t)row*128 + colb] = make_float2(v0, v1);
                } else if (MODE == 2) {
                    *(uint2*)&g_h1[(size_t)row*512 + o0 + colb]
                        = make_uint2(f2tf32(v0), f2tf32(v1));
                } else {
                    *(float2*)&g_u[(size_t)row*128 + colb] = make_float2(v0, v1);
                }
                if (MODE == 1 || MODE == 3) {
                    s[nt][0] += v0; s[nt][1] += v1;
                    q2[nt][0] += v0*v0; q2[nt][1] += v1*v1;
                }
            }
        }
    }

    if (MODE == 1 || MODE == 3) {
#pragma unroll
        for (int nt = 0; nt < 8; nt++) {
#pragma unroll
            for (int j = 0; j < 2; j++) {
                float a0 = s[nt][j], a1 = q2[nt][j];
#pragma unroll
                for (int off = 4; off < 32; off <<= 1) {
                    a0 += __shfl_xor_sync(0xffffffffu, a0, off);
                    a1 += __shfl_xor_sync(0xffffffffu, a1, off);
                }
                if (g == 0) {
                    const int col = (wn*8 + nt)*8 + tq*2 + j;
                    red[col*4 + wm]       = a0;
                    red[512 + col*4 + wm] = a1;
                }
            }
        }
        __syncthreads();
        if (tx < 128) {
            const int col = tx;
            float ssum = 0.f, ssq = 0.f;
#pragma unroll
            for (int wm2 = 0; wm2 < 4; wm2++) {
                ssum += red[col*4 + wm2];
                ssq  += red[512 + col*4 + wm2];
            }
            g_part[blockIdx.x*256 + col]       = ssum;
            g_part[blockIdx.x*256 + 128 + col] = ssq;
        }
    }
}

// ---------------- attention: smem-staged, split score/AV phases -----------
// K tile: row stride 17, plane 548 (scalar score reads, conflict-free —
//   verified round-14 layout). Q reads: float4 BROADCAST (1 wf/instr).
// V tile: row stride 16, plane 524 (float4 staging, LDS.64 phase-B reads).
#define RSK  17
#define PSK  548
#define RSV  16
#define PSV  524
__global__ __launch_bounds__(256) void attn_smem(const float* __restrict__ rpb) {
    __shared__ float Ks[9*PSK];
    __shared__ float Vs[9*PSV];
    __shared__ float Qs[32*16];
    __shared__ float Ps[32*28];     // scaled probs per z
    __shared__ float rpbs[125];

    const int cw = blockIdx.x;
    const int h  = blockIdx.y;
    const int hh = cw >> 5, ww = cw & 31;
    const int sh = min(max(hh-1, 0), 29);
    const int sw = min(max(ww-1, 0), 29);
    const int t = threadIdx.x;
    const size_t hb = (size_t)h * (NTOK*HD);

    for (int idx = t; idx < 1152; idx += 256) {
        const int col = idx >> 7;
        const int rem = idx & 127;
        const int a = col/3, b = col - a*3;
        const int nbase = ((sh+a)*32 + (sw+b))*32;
        const int z = rem >> 2, c4 = rem & 3;
        float4 kv = *(const float4*)&g_k[hb + (size_t)nbase*16 + rem*4];
        float4 vv = *(const float4*)&g_v[hb + (size_t)nbase*16 + rem*4];
        float* dk = &Ks[col*PSK + z*RSK + c4*4];
        dk[0]=kv.x; dk[1]=kv.y; dk[2]=kv.z; dk[3]=kv.w;
        *(float4*)&Vs[col*PSV + z*RSV + c4*4] = vv;
    }
    if (t < 128) {
        const int z = t >> 2, c4 = t & 3;
        float4 qv = *(const float4*)&g_q[hb + (size_t)(cw*32 + z)*16 + c4*4];
        float* dq = &Qs[z*16 + c4*4];
        dq[0]=qv.x*0.25f; dq[1]=qv.y*0.25f; dq[2]=qv.z*0.25f; dq[3]=qv.w*0.25f;
    }
    if (t < 125) rpbs[t] = rpb[h*125 + t];
    __syncthreads();

    // ---- phase A: scores + softmax, store scaled probs ----
    const int w = t >> 5, lane = t & 31;
    int a = 0, b = 0, jz = 0;
    if (lane < 27) { a = lane/9; b = (lane - a*9)/3; jz = lane - a*9 - b*3; }
    const int colp = a*3 + b;
    const int rh = sh + a - hh + 2;
    const int rw = sw + b - ww + 2;

#pragma unroll 1
    for (int tz = 0; tz < 4; tz++) {
        const int z  = w*4 + tz;
        const int sz = min(max(z-1, 0), 29);
        // Q via 4x float4 broadcast (all lanes same address => 1 wf each)
        const float4* qr = (const float4*)&Qs[z*16];
        const float4 q0 = qr[0], q1 = qr[1], q2 = qr[2], q3 = qr[3];
        float sc = -1e30f;
        if (lane < 27) {
            const float* kr = &Ks[colp*PSK + (sz+jz)*RSK];
            float sdot = q0.x*kr[0]  + q0.y*kr[1]  + q0.z*kr[2]  + q0.w*kr[3]
                       + q1.x*kr[4]  + q1.y*kr[5]  + q1.z*kr[6]  + q1.w*kr[7]
                       + q2.x*kr[8]  + q2.y*kr[9]  + q2.z*kr[10] + q2.w*kr[11]
                       + q3.x*kr[12] + q3.y*kr[13] + q3.z*kr[14] + q3.w*kr[15];
            const int rz = sz + jz - z + 2;
            sc = sdot + rpbs[(rh*5 + rw)*5 + rz];
        }
        float mx = sc;
#pragma unroll
        for (int off = 16; off; off >>= 1) mx = fmaxf(mx, __shfl_xor_sync(0xffffffffu, mx, off));
        float p = (lane < 27) ? __expf(sc - mx) : 0.f;
        float su = p;
#pragma unroll
        for (int off = 16; off; off >>= 1) su += __shfl_xor_sync(0xffffffffu, su, off);
        if (lane < 27) Ps[z*28 + lane] = p / su;
    }
    __syncthreads();

    // ---- phase B: AV, thread = (z, channel-pair) ----
    const int z2 = t >> 3;          // 0..31
    const int cp = t & 7;           // 0..7
    const int sz2 = min(max(z2-1, 0), 29);
    float ax = 0.f, ay = 0.f;
#pragma unroll
    for (int j = 0; j < 27; j++) {
        const int cj = j / 3;       // compile-time
        const int zj = j % 3;       // compile-time
        const float pj = Ps[z2*28 + j];
        const float2 v2 = *(const float2*)&Vs[cj*PSV + (sz2+zj)*RSV + cp*2];
        ax += pj * v2.x;
        ay += pj * v2.y;
    }
    *(uint2*)&g_attn[(size_t)(cw*32 + z2)*128 + h*16 + cp*2]
        = make_uint2(f2tf32(ax), f2tf32(ay));
}

// ---------------- final reduce: 256 partial blocks -> stats (1024 thr) ----
__global__ __launch_bounds__(1024) void reduce_final() {
    __shared__ float red[1024];
    const int t = threadIdx.x;
    const int slot = t & 255, part = t >> 8;   // 4 parts x 64 blocks
    float s = 0.f;
#pragma unroll 8
    for (int bx = part*64; bx < part*64 + 64; bx++) s += g_part[bx*256 + slot];
    red[part*256 + slot] = s;
    __syncthreads();
    if (t < 256) g_stats[t] = red[t] + red[256+t] + red[512+t] + red[768+t];
}

// ---------------- norm1 applied to g_y -> g_t (tf32 bits) ----------------
__global__ __launch_bounds__(256) void norm_tf32() {
    const int idx = blockIdx.x*256 + threadIdx.x;
    const int c = idx & 127;
    float m   = g_stats[c]     * INVN;
    float var = g_stats[c+128] * INVN - m*m;
    g_t[idx] = f2tf32((g_y[idx] - m) * rsqrtf(var + EPSF));
}

// ---------------- final instance-norm + transpose to [C][N] ----------------
__global__ __launch_bounds__(256) void norm_transpose(float* __restrict__ out) {
    __shared__ float tile[32][33];
    const int n0 = blockIdx.x*32, c0 = blockIdx.y*32;
    const int txx = threadIdx.x & 31, tyy = threadIdx.x >> 5;
    const int c = c0 + txx;
    float m   = g_stats[c]     * INVN;
    float var = g_stats[c+128] * INVN - m*m;
    float rs  = rsqrtf(var + EPSF);
#pragma unroll
    for (int r = 0; r < 32; r += 8)
        tile[tyy+r][txx] = (g_u[(size_t)(n0+tyy+r)*128 + c] - m) * rs;
    __syncthreads();
#pragma unroll
    for (int r = 0; r < 32; r += 8)
        out[(size_t)(c0+tyy+r)*NTOK + n0 + txx] = tile[txx][tyy+r];
}

// ---------------- launch ----------------
extern "C" void kernel_launch(void* const* d_in, const int* in_sizes, int n_in,
                              void* d_out, int out_size) {
    const float* x      = (const float*)d_in[0];
    const float* w_qkv  = (const float*)d_in[1];
    const float* b_qkv  = (const float*)d_in[2];
    const float* rpb    = (const float*)d_in[3];
    const float* w_proj = (const float*)d_in[4];
    const float* b_proj = (const float*)d_in[5];
    const float* w_ffn1 = (const float*)d_in[6];
    const float* b_ffn1 = (const float*)d_in[7];
    const float* w_ffn2 = (const float*)d_in[8];
    const float* b_ffn2 = (const float*)d_in[9];
    float* out = (float*)d_out;

    cvt_all<<<768, 256>>>(w_qkv, w_proj, w_ffn1, w_ffn2);
    transpose_x<<<dim3(NTOK/32, CCH/32), 256>>>(x);
    mma_gemm<128,0><<<dim3(256, 3), 256>>>(b_qkv);
    attn_smem<<<dim3(1024, NHEADS), 256>>>(rpb);
    mma_gemm<128,1><<<dim3(256, 1), 256>>>(b_proj);
    reduce_final<<<1, 1024>>>();
    norm_tf32<<<NTOK*CCH/256, 256>>>();
    mma_gemm<128,2><<<dim3(256, 4), 256>>>(b_ffn1);
    mma_gemm<512,3><<<dim3(256, 1), 256>>>(b_ffn2);
    reduce_final<<<1, 1024>>>();
    norm_transpose<<<dim3(NTOK/32, CCH/32), 256>>>(out);
}